// round 2
// baseline (speedup 1.0000x reference)
#include <cuda_runtime.h>
#include <math.h>

#define N_NODES 50000
#define N_EDGES 800000
#define FEAT    128

// Scratch in device globals (allocation inside kernel_launch is forbidden).
__device__ float g_e[N_NODES];       // per-node score e = x @ a
__device__ float g_m[N_NODES];       // segment max
__device__ float g_denom[N_NODES];   // segment sum of exp
__device__ float g_ex[N_EDGES];      // per-edge exp(vals - m[row])
__device__ float g_vals[N_EDGES];    // per-edge e[col]

// Float atomic max via sign-split int/uint trick. Valid for mixed signs
// given init = -inf.
__device__ __forceinline__ void atomicMaxF(float* addr, float val) {
    if (val >= 0.0f) {
        atomicMax((int*)addr, __float_as_int(val));
    } else {
        atomicMin((unsigned int*)addr, __float_as_uint(val));
    }
}

// K0: zero output, init m = -inf, denom = 0
__global__ void k_init(float* __restrict__ h) {
    int tid = blockIdx.x * blockDim.x + threadIdx.x;
    int stride = gridDim.x * blockDim.x;
    float4 z = make_float4(0.f, 0.f, 0.f, 0.f);
    for (int j = tid; j < N_NODES * FEAT / 4; j += stride)
        ((float4*)h)[j] = z;
    for (int j = tid; j < N_NODES; j += stride) {
        g_m[j] = -INFINITY;
        g_denom[j] = 0.0f;
    }
}

// K1: e[i] = dot(x[i,:], a)  — one warp per node, float4 loads
__global__ void k_score(const float* __restrict__ x, const float* __restrict__ a) {
    __shared__ float sa[FEAT];
    int tid = threadIdx.x;
    if (tid < FEAT) sa[tid] = a[tid];
    __syncthreads();
    int gwarp = (blockIdx.x * blockDim.x + tid) >> 5;
    int lane = tid & 31;
    if (gwarp >= N_NODES) return;
    float4 v = ((const float4*)x)[gwarp * 32 + lane];
    float4 w = ((const float4*)sa)[lane];
    float s = v.x * w.x + v.y * w.y + v.z * w.z + v.w * w.w;
    #pragma unroll
    for (int o = 16; o; o >>= 1) s += __shfl_xor_sync(0xffffffffu, s, o);
    if (lane == 0) g_e[gwarp] = s;
}

// K2: vals[k] = e[col[k]]; segment max into m[row[k]]
__global__ void k_edge_max(const int* __restrict__ row,
                           const int* __restrict__ col) {
    int k = blockIdx.x * blockDim.x + threadIdx.x;
    if (k >= N_EDGES) return;
    float v = g_e[col[k]];
    g_vals[k] = v;
    atomicMaxF(&g_m[row[k]], v);
}

// K3: empty rows (m still -inf / non-finite) -> 0
__global__ void k_fix_m() {
    int i = blockIdx.x * blockDim.x + threadIdx.x;
    if (i >= N_NODES) return;
    float m = g_m[i];
    if (!isfinite(m)) g_m[i] = 0.0f;
}

// K4: ex[k] = exp(vals[k] - m[row[k]]); denom[row] += ex
__global__ void k_edge_exp(const int* __restrict__ row) {
    int k = blockIdx.x * blockDim.x + threadIdx.x;
    if (k >= N_EDGES) return;
    int r = row[k];
    float ex = __expf(g_vals[k] - g_m[r]);
    g_ex[k] = ex;
    atomicAdd(&g_denom[r], ex);
}

// K5: h[row] += (ex/denom[row]) * x[col]  — one warp per edge,
// float4 gather + red.global.add.v4.f32 scatter (sm_90+ vector reduction).
__global__ void k_scatter(const float* __restrict__ x,
                          const int* __restrict__ row,
                          const int* __restrict__ col,
                          float* __restrict__ h) {
    int gwarp = (blockIdx.x * blockDim.x + threadIdx.x) >> 5;
    int lane = threadIdx.x & 31;
    if (gwarp >= N_EDGES) return;
    int r = row[gwarp];
    int c = col[gwarp];
    float att = g_ex[gwarp] / g_denom[r];
    float4 v = ((const float4*)x)[c * 32 + lane];
    float* dst = h + (size_t)r * FEAT + lane * 4;
    asm volatile("red.global.add.v4.f32 [%0], {%1, %2, %3, %4};"
                 :: "l"(dst),
                    "f"(att * v.x), "f"(att * v.y),
                    "f"(att * v.z), "f"(att * v.w)
                 : "memory");
}

extern "C" void kernel_launch(void* const* d_in, const int* in_sizes, int n_in,
                              void* d_out, int out_size) {
    const float* x   = (const float*)d_in[0];  // [N_NODES, FEAT]
    const float* a   = (const float*)d_in[1];  // [FEAT, 1]
    const int*   row = (const int*)d_in[2];    // [N_EDGES] int32 (JAX x64 off)
    const int*   col = (const int*)d_in[3];    // [N_EDGES] int32
    float* h = (float*)d_out;                  // [N_NODES, FEAT]

    k_init<<<1024, 256>>>(h);

    // one warp per node: N_NODES warps
    int score_blocks = (N_NODES * 32 + 255) / 256;
    k_score<<<score_blocks, 256>>>(x, a);

    int edge_blocks = (N_EDGES + 255) / 256;
    k_edge_max<<<edge_blocks, 256>>>(row, col);

    int node_blocks = (N_NODES + 255) / 256;
    k_fix_m<<<node_blocks, 256>>>();

    k_edge_exp<<<edge_blocks, 256>>>(row);

    // one warp per edge: N_EDGES warps
    int scat_blocks = (N_EDGES * 32 + 255) / 256;
    k_scatter<<<scat_blocks, 256>>>(x, row, col, h);
}

// round 3
// speedup vs baseline: 1.7857x; 1.7857x over previous
#include <cuda_runtime.h>
#include <math.h>

#define N_NODES 50000
#define N_EDGES 800000
#define FEAT    128
#define SCAN_BLOCKS 196   // ceil(50000/256)

// Scratch (device globals; no allocation allowed in kernel_launch).
__device__ float g_e[N_NODES];            // e = x @ a
__device__ int   g_cnt[N_NODES];          // degree
__device__ int   g_cursor[N_NODES];       // fill cursor
__device__ int   g_rowptr[N_NODES + 1];   // CSR row pointers
__device__ int   g_blocksum[SCAN_BLOCKS]; // scan partials
__device__ int   g_cidx[N_EDGES];         // CSR column indices

// K1: e[i] = dot(x[i,:], a); also zero the degree counters.
__global__ void k_score(const float* __restrict__ x, const float* __restrict__ a) {
    __shared__ float sa[FEAT];
    int tid = threadIdx.x;
    if (tid < FEAT) sa[tid] = a[tid];
    __syncthreads();
    int gt = blockIdx.x * blockDim.x + tid;
    if (gt < N_NODES) g_cnt[gt] = 0;
    int gwarp = gt >> 5;
    int lane = tid & 31;
    if (gwarp >= N_NODES) return;
    float4 v = ((const float4*)x)[gwarp * 32 + lane];
    float4 w = ((const float4*)sa)[lane];
    float s = v.x * w.x + v.y * w.y + v.z * w.z + v.w * w.w;
    #pragma unroll
    for (int o = 16; o; o >>= 1) s += __shfl_xor_sync(0xffffffffu, s, o);
    if (lane == 0) g_e[gwarp] = s;
}

// K2: degree histogram
__global__ void k_count(const int* __restrict__ row) {
    int k = blockIdx.x * blockDim.x + threadIdx.x;
    if (k >= N_EDGES) return;
    atomicAdd(&g_cnt[row[k]], 1);
}

// K3a: per-block exclusive scan of g_cnt -> g_rowptr, block totals -> g_blocksum
__global__ void k_scan1() {
    int i = blockIdx.x * 256 + threadIdx.x;
    int v = (i < N_NODES) ? g_cnt[i] : 0;
    int lane = threadIdx.x & 31, w = threadIdx.x >> 5;
    int s = v;
    #pragma unroll
    for (int o = 1; o < 32; o <<= 1) {
        int t = __shfl_up_sync(0xffffffffu, s, o);
        if (lane >= o) s += t;
    }
    __shared__ int ws[8];
    if (lane == 31) ws[w] = s;
    __syncthreads();
    if (w == 0) {
        int t = (lane < 8) ? ws[lane] : 0;
        #pragma unroll
        for (int o = 1; o < 8; o <<= 1) {
            int u = __shfl_up_sync(0xffffffffu, t, o);
            if (lane >= o) t += u;
        }
        if (lane < 8) ws[lane] = t;
    }
    __syncthreads();
    int excl = s - v + (w > 0 ? ws[w - 1] : 0);
    if (i < N_NODES) g_rowptr[i] = excl;
    if (threadIdx.x == 0) g_blocksum[blockIdx.x] = ws[7];
}

// K3b: exclusive scan of block sums (single block)
__global__ void k_scan2() {
    int i = threadIdx.x;
    int v = (i < SCAN_BLOCKS) ? g_blocksum[i] : 0;
    int lane = i & 31, w = i >> 5;
    int s = v;
    #pragma unroll
    for (int o = 1; o < 32; o <<= 1) {
        int t = __shfl_up_sync(0xffffffffu, s, o);
        if (lane >= o) s += t;
    }
    __shared__ int ws[8];
    if (lane == 31) ws[w] = s;
    __syncthreads();
    if (w == 0) {
        int t = (lane < 8) ? ws[lane] : 0;
        #pragma unroll
        for (int o = 1; o < 8; o <<= 1) {
            int u = __shfl_up_sync(0xffffffffu, t, o);
            if (lane >= o) t += u;
        }
        if (lane < 8) ws[lane] = t;
    }
    __syncthreads();
    int excl = s - v + (w > 0 ? ws[w - 1] : 0);
    if (i < SCAN_BLOCKS) g_blocksum[i] = excl;
}

// K3c: add block offsets, zero cursors, cap rowptr
__global__ void k_scan3() {
    int i = blockIdx.x * 256 + threadIdx.x;
    if (i < N_NODES) {
        g_rowptr[i] += g_blocksum[i >> 8];
        g_cursor[i] = 0;
    }
    if (i == 0) g_rowptr[N_NODES] = N_EDGES;
}

// K4: counting-sort fill of column indices
__global__ void k_fill(const int* __restrict__ row, const int* __restrict__ col) {
    int k = blockIdx.x * blockDim.x + threadIdx.x;
    if (k >= N_EDGES) return;
    int r = row[k];
    int pos = g_rowptr[r] + atomicAdd(&g_cursor[r], 1);
    g_cidx[pos] = col[k];
}

// K5: warp per row — softmax over the row's edges + weighted feature gather,
// register accumulator, single float4 store per lane. No atomics.
__global__ void k_row(const float* __restrict__ x, float* __restrict__ h) {
    int gw = (blockIdx.x * blockDim.x + threadIdx.x) >> 5;
    int lane = threadIdx.x & 31;
    if (gw >= N_NODES) return;
    int s0 = g_rowptr[gw], s1 = g_rowptr[gw + 1];

    // pass A: row max
    float m = -INFINITY;
    for (int i = s0 + lane; i < s1; i += 32) m = fmaxf(m, g_e[g_cidx[i]]);
    #pragma unroll
    for (int o = 16; o; o >>= 1) m = fmaxf(m, __shfl_xor_sync(0xffffffffu, m, o));
    if (!isfinite(m)) m = 0.0f;

    // pass B: denom
    float ssum = 0.0f;
    for (int i = s0 + lane; i < s1; i += 32) ssum += __expf(g_e[g_cidx[i]] - m);
    #pragma unroll
    for (int o = 16; o; o >>= 1) ssum += __shfl_xor_sync(0xffffffffu, ssum, o);
    float inv = (s1 > s0) ? 1.0f / ssum : 0.0f;

    // pass C: weighted accumulate (serial over row's edges, broadcast loads)
    float4 acc = make_float4(0.f, 0.f, 0.f, 0.f);
    for (int i = s0; i < s1; i++) {
        int c = g_cidx[i];
        float att = __expf(g_e[c] - m) * inv;
        float4 v = ((const float4*)x)[c * 32 + lane];
        acc.x += att * v.x;
        acc.y += att * v.y;
        acc.z += att * v.z;
        acc.w += att * v.w;
    }
    ((float4*)h)[gw * 32 + lane] = acc;
}

extern "C" void kernel_launch(void* const* d_in, const int* in_sizes, int n_in,
                              void* d_out, int out_size) {
    const float* x   = (const float*)d_in[0];  // [N_NODES, FEAT]
    const float* a   = (const float*)d_in[1];  // [FEAT, 1]
    const int*   row = (const int*)d_in[2];    // [N_EDGES] int32
    const int*   col = (const int*)d_in[3];    // [N_EDGES] int32
    float* h = (float*)d_out;                  // [N_NODES, FEAT]

    int score_blocks = (N_NODES * 32 + 255) / 256;   // warp per node
    k_score<<<score_blocks, 256>>>(x, a);

    int edge_blocks = (N_EDGES + 255) / 256;
    k_count<<<edge_blocks, 256>>>(row);

    k_scan1<<<SCAN_BLOCKS, 256>>>();
    k_scan2<<<1, 256>>>();
    k_scan3<<<SCAN_BLOCKS, 256>>>();

    k_fill<<<edge_blocks, 256>>>(row, col);

    int row_blocks = (N_NODES * 32 + 255) / 256;     // warp per row
    k_row<<<row_blocks, 256>>>(x, h);
}